// round 9
// baseline (speedup 1.0000x reference)
#include <cuda_runtime.h>
#include <cuda_fp16.h>
#include <cstdint>
#include <cstddef>

#define DEV __device__ __forceinline__

// ---------------- scratch (static device allocations: allowed) ----------------
__device__ __half g_W0h[4096u * 1024u];  // 8 MB, W0^T [out=4096][in=1024] fp16
__device__ __half g_W1h[1024u * 4096u];  // 8 MB, W1^T [out=1024][in=4096] fp16
__device__ __half g_Xh [8192u * 1024u];  // 16 MB, fp16 x
__device__ __half g_Hh [8192u * 4096u];  // 64 MB, fp16 gelu(h)

// ---------------- helpers ----------------
DEV uint32_t smem_u32(const void* p) { return (uint32_t)__cvta_generic_to_shared(p); }
DEV void cp_async16(uint32_t dst, const void* src) {
    asm volatile("cp.async.cg.shared.global [%0], [%1], 16;\n" :: "r"(dst), "l"(src));
}
DEV void cp_commit() { asm volatile("cp.async.commit_group;\n" ::: "memory"); }
template <int W> DEV void cp_wait() {
    asm volatile("cp.async.wait_group %0;\n" :: "n"(W) : "memory");
}
DEV void bar_named(int id) {   // 128-thread named barrier
    asm volatile("bar.sync %0, 128;" :: "r"(id) : "memory");
}
DEV void mma_f16(float* c, const uint32_t* a, const uint32_t b0, const uint32_t b1) {
    asm volatile(
        "mma.sync.aligned.m16n8k16.row.col.f32.f16.f16.f32 "
        "{%0,%1,%2,%3}, {%4,%5,%6,%7}, {%8,%9}, {%0,%1,%2,%3};\n"
        : "+f"(c[0]), "+f"(c[1]), "+f"(c[2]), "+f"(c[3])
        : "r"(a[0]), "r"(a[1]), "r"(a[2]), "r"(a[3]), "r"(b0), "r"(b1));
}
DEV void ldsm_x4(uint32_t* r, uint32_t addr) {
    asm volatile("ldmatrix.sync.aligned.m8n8.x4.shared.b16 {%0,%1,%2,%3}, [%4];"
                 : "=r"(r[0]), "=r"(r[1]), "=r"(r[2]), "=r"(r[3]) : "r"(addr));
}
// exact-erf gelu via the cheap erff polynomial path
DEV float gelu_exact(float x) {
    return 0.5f * x * (1.0f + erff(x * 0.70710678118654752f));
}

// ---------------- prologue: x (fp32) -> fp16 ----------------
__global__ void k_x_to_h(const float4* __restrict__ x, __half2* __restrict__ xh, int n4) {
    int idx = blockIdx.x * blockDim.x + threadIdx.x;
    if (idx < n4) {
        float4 v = x[idx];
        xh[2 * idx]     = __floats2half2_rn(v.x, v.y);
        xh[2 * idx + 1] = __floats2half2_rn(v.z, v.w);
    }
}

// ---------------- transposed TT weight builders (fp16 out, proven correct) ----
__global__ void k_build_w0t(const float* __restrict__ c0a,
                            const float* __restrict__ c0b,
                            const float* __restrict__ c0c) {
    __shared__ float a_sh[64], c_sh[64], b_sh[1024], bc[1024];
    const int m = blockIdx.x;
    const int o = m >> 8, p = (m >> 4) & 15, q = m & 15;
    const int t = threadIdx.x;

    if (t < 64) {                       // a_sh[i*8+r]
        int i = t >> 3, r = t & 7;
        a_sh[t] = c0a[(i * 16 + o) * 8 + r];
    } else if (t < 128) {               // c_sh[s*8+k]
        int tt = t - 64, s = tt >> 3, k = tt & 7;
        c_sh[tt] = c0c[(s * 8 + k) * 16 + q];
    }
    for (int idx = t; idx < 1024; idx += 256) {   // b_sh[(r*16+j)*8+s]
        int rj = idx >> 3, s = idx & 7;
        b_sh[idx] = c0b[(rj * 16 + p) * 8 + s];
    }
    __syncthreads();
    for (int idx = t; idx < 1024; idx += 256) {   // bc[(r*16+j)*8+k]
        int rj = idx >> 3, k = idx & 7;
        float acc = 0.f;
#pragma unroll
        for (int s = 0; s < 8; s++) acc = fmaf(b_sh[rj * 8 + s], c_sh[s * 8 + k], acc);
        bc[idx] = acc;
    }
    __syncthreads();
    float v[4];
#pragma unroll
    for (int d = 0; d < 4; d++) {
        int n = 4 * t + d;
        int i = n >> 7, j = (n >> 3) & 15, k = n & 7;
        float acc = 0.f;
#pragma unroll
        for (int r = 0; r < 8; r++) acc = fmaf(a_sh[i * 8 + r], bc[(r * 16 + j) * 8 + k], acc);
        v[d] = acc;
    }
    __half2* dst = reinterpret_cast<__half2*>(&g_W0h[(size_t)m * 1024 + 4 * t]);
    dst[0] = __floats2half2_rn(v[0], v[1]);
    dst[1] = __floats2half2_rn(v[2], v[3]);
}

__global__ void k_build_w1t(const float* __restrict__ c1a,
                            const float* __restrict__ c1b,
                            const float* __restrict__ c1c) {
    __shared__ float a_sh[128], c_sh[128], b_sh[1024], bc[2048];
    const int m = blockIdx.x;
    const int o = m >> 7, p = (m >> 3) & 15, q = m & 7;
    const int t = threadIdx.x;

    if (t < 128) {                      // a_sh[i*8+r]
        int i = t >> 3, r = t & 7;
        a_sh[t] = c1a[(i * 8 + o) * 8 + r];
    } else {                            // c_sh[s*16+k]
        int tt = t - 128, s = tt >> 4, k = tt & 15;
        c_sh[tt] = c1c[(s * 16 + k) * 8 + q];
    }
    for (int idx = t; idx < 1024; idx += 256) {   // b_sh[(r*16+j)*8+s]
        int rj = idx >> 3, s = idx & 7;
        b_sh[idx] = c1b[(rj * 16 + p) * 8 + s];
    }
    __syncthreads();
    for (int idx = t; idx < 2048; idx += 256) {   // bc[(r*16+j)*16+k]
        int rj = idx >> 4, k = idx & 15;
        float acc = 0.f;
#pragma unroll
        for (int s = 0; s < 8; s++) acc = fmaf(b_sh[rj * 8 + s], c_sh[s * 16 + k], acc);
        bc[idx] = acc;
    }
    __syncthreads();
    const int i = t >> 4, j = t & 15;   // n = 16t + k
    float v[16];
#pragma unroll
    for (int k = 0; k < 16; k++) {
        float acc = 0.f;
#pragma unroll
        for (int r = 0; r < 8; r++) acc = fmaf(a_sh[i * 8 + r], bc[(r * 16 + j) * 16 + k], acc);
        v[k] = acc;
    }
    __half2* dst = reinterpret_cast<__half2*>(&g_W1h[(size_t)m * 4096 + 16 * t]);
#pragma unroll
    for (int d = 0; d < 8; d++)
        dst[d] = __floats2half2_rn(v[2 * d], v[2 * d + 1]);
}

// ---------------- fp16 GEMM: C = act(A @ B^T + bias) ----------------
// A: [M][K] fp16 row-major; B: [N][K] fp16 row-major (weights pre-transposed).
// BM=BN=128, BK=64 halves, 3-stage cp.async ring, ldmatrix.x4 feed.
// 512 threads = 16 warps; warp (i,j): wm=32j (j=warp&3), wn=32i (i=warp>>2).
// Pod-partitioned pipeline: A rows [32j,32j+32) are copied AND read only by the
// 4 warps with wm=j; B rows [32i,32i+32) only by the 4 warps with wn=i. The
// CTA-wide __syncthreads is replaced by two 128-thread named barriers, so
// 4-warp pods drift out of phase (crossbar and tensor pipe overlap in time).
constexpr int BM = 128, BN = 128, BKH = 64, STAGES = 3;
constexpr int STRW = 36;                               // 32 words + 4 pad
constexpr int ROWB = STRW * 4;                         // 144 B row stride
constexpr int A_WORDS = BM * STRW;                     // 4608
constexpr int B_WORDS = BN * STRW;                     // 4608
constexpr int STAGE_WORDS = A_WORDS + B_WORDS;         // 9216
constexpr int STAGE_BYTES = STAGE_WORDS * 4;
constexpr uint32_t STAGE_LAST = 2u * STAGE_BYTES;
constexpr int GEMM_SMEM = STAGES * STAGE_BYTES;        // 110592 B

template <bool FUSE_GELU, bool HALF_OUT>
__global__ void __launch_bounds__(512, 2)
k_gemm_f16(const __half* __restrict__ A, const __half* __restrict__ Bg,
           const float* __restrict__ bias, void* __restrict__ Cv,
           int M, int N, int K) {
    extern __shared__ uint32_t smem_w[];
    const uint32_t sbase = smem_u32(smem_w);

    const int tid = threadIdx.x;
    const int m0 = blockIdx.y * BM;
    const int n0 = blockIdx.x * BN;
    const int lane = tid & 31;
    const int warp = tid >> 5;
    const int g = lane >> 2, tig = lane & 3;
    const int jset = warp & 3;             // wm-set
    const int iset = warp >> 2;            // wn-set
    const int wm = jset * 32;
    const int wn = iset * 32;

    const int T = K / BKH;

    // ---- pod-partitioned cp.async duties ----
    // A set j: 128 threads (warps (*,j)) fill rows [32j,32j+32), 128B each.
    const int aIdx = iset * 32 + lane;             // 0..127 within A-set
    const int arow = wm + (aIdx >> 2);
    const int acw  = (aIdx & 3) * 8;               // word col base (2 chunks)
    // B set i: 128 threads (warps (i,*)) fill rows [32i,32i+32).
    const int bIdx = jset * 32 + lane;
    const int brow = wn + (bIdx >> 2);
    const int bcw  = (bIdx & 3) * 8;

    const __half* aNext = A + (size_t)(m0 + arow) * K + acw * 2;
    const __half* bNext = Bg + (size_t)(n0 + brow) * K + bcw * 2;
    const uint32_t sa_off = (uint32_t)(arow * STRW + acw) * 4u;
    const uint32_t sb_off = (uint32_t)A_WORDS * 4u + (uint32_t)(brow * STRW + bcw) * 4u;

    auto issue_at = [&](uint32_t stoff) {
        const uint32_t sa = sbase + stoff + sa_off;
        const uint32_t sb = sbase + stoff + sb_off;
        cp_async16(sa,       aNext);
        cp_async16(sa + 16u, aNext + 8);
        cp_async16(sb,       bNext);
        cp_async16(sb + 16u, bNext + 8);
        cp_commit();
        aNext += BKH;
        bNext += BKH;
    };

    // ldmatrix base addresses (stage 0)
    const uint32_t aLdsm = sbase
        + (uint32_t)((wm + (lane & 15)) * ROWB)
        + (uint32_t)((lane >> 4) * 16);
    const uint32_t bLdsm = sbase + (uint32_t)A_WORDS * 4u
        + (uint32_t)((wn + ((lane >> 4) << 3) + (lane & 7)) * ROWB)
        + (uint32_t)(((lane >> 3) & 1) * 16);

    float acc[2][4][4];
#pragma unroll
    for (int mi = 0; mi < 2; mi++)
#pragma unroll
        for (int ni = 0; ni < 4; ni++)
#pragma unroll
            for (int q = 0; q < 4; q++) acc[mi][ni][q] = 0.f;

    issue_at(0);
    issue_at(STAGE_BYTES);

    uint32_t stoff_i = STAGE_LAST;    // smem offset for next issue (stage t+2)
    uint32_t stoff_c = 0;             // smem offset for current compute (stage t)

    for (int t = 0; t < T; ++t) {
        cp_wait<1>();                 // my stage-t chunks landed
        bar_named(8 + jset);          // A-pod: rows [wm,wm+32) ready; pod reads of t-1 done
        bar_named(12 + iset);         // B-pod: rows [wn,wn+32) ready; pod reads of t-1 done
        if (t + 2 < T) issue_at(stoff_i);
        stoff_i = (stoff_i == STAGE_LAST) ? 0u : stoff_i + (uint32_t)STAGE_BYTES;

        const uint32_t aS = aLdsm + stoff_c;
        const uint32_t bS = bLdsm + stoff_c;
        stoff_c = (stoff_c == STAGE_LAST) ? 0u : stoff_c + (uint32_t)STAGE_BYTES;
#pragma unroll
        for (int k16 = 0; k16 < 4; ++k16) {          // 4 x K=16 per stage
            const uint32_t kb = (uint32_t)(k16 * 32); // 8 words = 32 B
            uint32_t bq[2][4];
            ldsm_x4(bq[0], bS + kb);                  // B first: feeds all 8 MMAs
            ldsm_x4(bq[1], bS + (uint32_t)(16 * ROWB) + kb);
            uint32_t af[2][4];
            ldsm_x4(af[0], aS + kb);
            ldsm_x4(af[1], aS + (uint32_t)(16 * ROWB) + kb);
#pragma unroll
            for (int mi = 0; mi < 2; ++mi)
#pragma unroll
                for (int ni = 0; ni < 4; ++ni)
                    mma_f16(acc[mi][ni], af[mi], bq[ni >> 1][2 * (ni & 1)],
                            bq[ni >> 1][2 * (ni & 1) + 1]);
        }
    }

    // ---- epilogue ----
#pragma unroll
    for (int mi = 0; mi < 2; ++mi) {
        const int r0 = m0 + wm + mi * 16 + g;
#pragma unroll
        for (int ni = 0; ni < 4; ++ni) {
            const int col = n0 + wn + ni * 8 + tig * 2;
            const float bv0 = bias[col], bv1 = bias[col + 1];
            float v00 = acc[mi][ni][0] + bv0;
            float v01 = acc[mi][ni][1] + bv1;
            float v10 = acc[mi][ni][2] + bv0;
            float v11 = acc[mi][ni][3] + bv1;
            if (FUSE_GELU) {
                v00 = gelu_exact(v00);
                v01 = gelu_exact(v01);
                v10 = gelu_exact(v10);
                v11 = gelu_exact(v11);
            }
            if (HALF_OUT) {
                __half* C = (__half*)Cv;
                *reinterpret_cast<__half2*>(&C[(size_t)r0 * N + col]) =
                    __floats2half2_rn(v00, v01);
                *reinterpret_cast<__half2*>(&C[(size_t)(r0 + 8) * N + col]) =
                    __floats2half2_rn(v10, v11);
            } else {
                float* C = (float*)Cv;
                *reinterpret_cast<float2*>(&C[(size_t)r0 * N + col])       = make_float2(v00, v01);
                *reinterpret_cast<float2*>(&C[(size_t)(r0 + 8) * N + col]) = make_float2(v10, v11);
            }
        }
    }
}

// ---------------- launch ----------------
extern "C" void kernel_launch(void* const* d_in, const int* in_sizes, int n_in,
                              void* d_out, int out_size) {
    const float* x   = (const float*)d_in[0];
    const float* c0a = (const float*)d_in[1];
    const float* c0b = (const float*)d_in[2];
    const float* c0c = (const float*)d_in[3];
    const float* b0  = (const float*)d_in[4];
    const float* c1a = (const float*)d_in[5];
    const float* c1b = (const float*)d_in[6];
    const float* c1c = (const float*)d_in[7];
    const float* b1  = (const float*)d_in[8];
    float* out = (float*)d_out;

    void *pW0, *pW1, *pXh, *pHh;
    cudaGetSymbolAddress(&pW0, g_W0h);
    cudaGetSymbolAddress(&pW1, g_W1h);
    cudaGetSymbolAddress(&pXh, g_Xh);
    cudaGetSymbolAddress(&pHh, g_Hh);
    __half* W0h = (__half*)pW0;
    __half* W1h = (__half*)pW1;
    __half* Xh  = (__half*)pXh;
    __half* Hh  = (__half*)pHh;

    cudaFuncSetAttribute(k_gemm_f16<true, true>,
                         cudaFuncAttributeMaxDynamicSharedMemorySize, GEMM_SMEM);
    cudaFuncSetAttribute(k_gemm_f16<false, false>,
                         cudaFuncAttributeMaxDynamicSharedMemorySize, GEMM_SMEM);

    // 1) convert x -> fp16
    k_x_to_h<<<2048, 1024>>>((const float4*)x, (__half2*)Xh, 8192 * 1024 / 4);
    // 2) materialize transposed TT weight matrices (fp16)
    k_build_w0t<<<4096, 256>>>(c0a, c0b, c0c);
    k_build_w1t<<<1024, 256>>>(c1a, c1b, c1c);
    // 3) Hh = fp16(gelu(Xh @ W0h^T + b0))   [8192 x 4096]
    k_gemm_f16<true, true><<<dim3(4096 / BN, 8192 / BM), 512, GEMM_SMEM>>>(
        Xh, W0h, b0, Hh, 8192, 4096, 1024);
    // 4) out = Hh @ W1h^T + b1              [8192 x 1024] fp32
    k_gemm_f16<false, false><<<dim3(1024 / BN, 8192 / BM), 512, GEMM_SMEM>>>(
        Hh, W1h, b1, out, 8192, 1024, 4096);
}

// round 10
// speedup vs baseline: 1.1204x; 1.1204x over previous
#include <cuda_runtime.h>
#include <cuda_fp16.h>
#include <cstdint>
#include <cstddef>

#define DEV __device__ __forceinline__

// ---------------- scratch (static device allocations: allowed) ----------------
__device__ __half g_W0h[4096u * 1024u];  // 8 MB, W0^T [out=4096][in=1024] fp16
__device__ __half g_W1h[1024u * 4096u];  // 8 MB, W1^T [out=1024][in=4096] fp16
__device__ __half g_Xh [8192u * 1024u];  // 16 MB, fp16 x
__device__ __half g_Hh [8192u * 4096u];  // 64 MB, fp16 gelu(h)

// ---------------- helpers ----------------
DEV uint32_t smem_u32(const void* p) { return (uint32_t)__cvta_generic_to_shared(p); }
DEV void cp_async16(uint32_t dst, const void* src) {
    asm volatile("cp.async.cg.shared.global [%0], [%1], 16;\n" :: "r"(dst), "l"(src));
}
DEV void cp_commit() { asm volatile("cp.async.commit_group;\n" ::: "memory"); }
template <int W> DEV void cp_wait() {
    asm volatile("cp.async.wait_group %0;\n" :: "n"(W) : "memory");
}
DEV void mma_f16(float* c, const uint32_t* a, const uint32_t b0, const uint32_t b1) {
    asm volatile(
        "mma.sync.aligned.m16n8k16.row.col.f32.f16.f16.f32 "
        "{%0,%1,%2,%3}, {%4,%5,%6,%7}, {%8,%9}, {%0,%1,%2,%3};\n"
        : "+f"(c[0]), "+f"(c[1]), "+f"(c[2]), "+f"(c[3])
        : "r"(a[0]), "r"(a[1]), "r"(a[2]), "r"(a[3]), "r"(b0), "r"(b1));
}
DEV void ldsm_x4(uint32_t* r, uint32_t addr) {
    asm volatile("ldmatrix.sync.aligned.m8n8.x4.shared.b16 {%0,%1,%2,%3}, [%4];"
                 : "=r"(r[0]), "=r"(r[1]), "=r"(r[2]), "=r"(r[3]) : "r"(addr));
}
// exact-erf gelu via the cheap erff polynomial path
DEV float gelu_exact(float x) {
    return 0.5f * x * (1.0f + erff(x * 0.70710678118654752f));
}

// ---------------- prologue: x (fp32) -> fp16 ----------------
__global__ void k_x_to_h(const float4* __restrict__ x, __half2* __restrict__ xh, int n4) {
    int idx = blockIdx.x * blockDim.x + threadIdx.x;
    if (idx < n4) {
        float4 v = x[idx];
        xh[2 * idx]     = __floats2half2_rn(v.x, v.y);
        xh[2 * idx + 1] = __floats2half2_rn(v.z, v.w);
    }
}

// ---------------- transposed TT weight builders (fp16 out, proven correct) ----
__global__ void k_build_w0t(const float* __restrict__ c0a,
                            const float* __restrict__ c0b,
                            const float* __restrict__ c0c) {
    __shared__ float a_sh[64], c_sh[64], b_sh[1024], bc[1024];
    const int m = blockIdx.x;
    const int o = m >> 8, p = (m >> 4) & 15, q = m & 15;
    const int t = threadIdx.x;

    if (t < 64) {                       // a_sh[i*8+r]
        int i = t >> 3, r = t & 7;
        a_sh[t] = c0a[(i * 16 + o) * 8 + r];
    } else if (t < 128) {               // c_sh[s*8+k]
        int tt = t - 64, s = tt >> 3, k = tt & 7;
        c_sh[tt] = c0c[(s * 8 + k) * 16 + q];
    }
    for (int idx = t; idx < 1024; idx += 256) {   // b_sh[(r*16+j)*8+s]
        int rj = idx >> 3, s = idx & 7;
        b_sh[idx] = c0b[(rj * 16 + p) * 8 + s];
    }
    __syncthreads();
    for (int idx = t; idx < 1024; idx += 256) {   // bc[(r*16+j)*8+k]
        int rj = idx >> 3, k = idx & 7;
        float acc = 0.f;
#pragma unroll
        for (int s = 0; s < 8; s++) acc = fmaf(b_sh[rj * 8 + s], c_sh[s * 8 + k], acc);
        bc[idx] = acc;
    }
    __syncthreads();
    float v[4];
#pragma unroll
    for (int d = 0; d < 4; d++) {
        int n = 4 * t + d;
        int i = n >> 7, j = (n >> 3) & 15, k = n & 7;
        float acc = 0.f;
#pragma unroll
        for (int r = 0; r < 8; r++) acc = fmaf(a_sh[i * 8 + r], bc[(r * 16 + j) * 8 + k], acc);
        v[d] = acc;
    }
    __half2* dst = reinterpret_cast<__half2*>(&g_W0h[(size_t)m * 1024 + 4 * t]);
    dst[0] = __floats2half2_rn(v[0], v[1]);
    dst[1] = __floats2half2_rn(v[2], v[3]);
}

__global__ void k_build_w1t(const float* __restrict__ c1a,
                            const float* __restrict__ c1b,
                            const float* __restrict__ c1c) {
    __shared__ float a_sh[128], c_sh[128], b_sh[1024], bc[2048];
    const int m = blockIdx.x;
    const int o = m >> 7, p = (m >> 3) & 15, q = m & 7;
    const int t = threadIdx.x;

    if (t < 128) {                      // a_sh[i*8+r]
        int i = t >> 3, r = t & 7;
        a_sh[t] = c1a[(i * 8 + o) * 8 + r];
    } else {                            // c_sh[s*16+k]
        int tt = t - 128, s = tt >> 4, k = tt & 15;
        c_sh[tt] = c1c[(s * 16 + k) * 8 + q];
    }
    for (int idx = t; idx < 1024; idx += 256) {   // b_sh[(r*16+j)*8+s]
        int rj = idx >> 3, s = idx & 7;
        b_sh[idx] = c1b[(rj * 16 + p) * 8 + s];
    }
    __syncthreads();
    for (int idx = t; idx < 2048; idx += 256) {   // bc[(r*16+j)*16+k]
        int rj = idx >> 4, k = idx & 15;
        float acc = 0.f;
#pragma unroll
        for (int s = 0; s < 8; s++) acc = fmaf(b_sh[rj * 8 + s], c_sh[s * 16 + k], acc);
        bc[idx] = acc;
    }
    __syncthreads();
    const int i = t >> 4, j = t & 15;   // n = 16t + k
    float v[16];
#pragma unroll
    for (int k = 0; k < 16; k++) {
        float acc = 0.f;
#pragma unroll
        for (int r = 0; r < 8; r++) acc = fmaf(a_sh[i * 8 + r], bc[(r * 16 + j) * 16 + k], acc);
        v[k] = acc;
    }
    __half2* dst = reinterpret_cast<__half2*>(&g_W1h[(size_t)m * 4096 + 16 * t]);
#pragma unroll
    for (int d = 0; d < 8; d++)
        dst[d] = __floats2half2_rn(v[2 * d], v[2 * d + 1]);
}

// ---------------- fp16 GEMM: C = act(A @ B^T + bias) ----------------
// A: [M][K] fp16 row-major; B: [N][K] fp16 row-major (weights pre-transposed).
// CTA tile 128(M) x 256(N), BK=64 halves, 3-stage cp.async ring.
// 256 threads = 8 warps in 2(M) x 4(N); warp tile 64x64 (acc 128 regs).
// 1 CTA/SM, big register budget -> ptxas can pipeline LDSM across k16 steps.
constexpr int BM = 128, BN = 256, BKH = 64, STAGES = 3;
constexpr int STRW = 36;                               // 32 words + 4 pad
constexpr int ROWB = STRW * 4;                         // 144 B row stride
constexpr int A_WORDS = BM * STRW;                     // 4608
constexpr int B_WORDS = BN * STRW;                     // 9216
constexpr int STAGE_WORDS = A_WORDS + B_WORDS;         // 13824
constexpr int STAGE_BYTES = STAGE_WORDS * 4;           // 55296
constexpr uint32_t STAGE_LAST = 2u * STAGE_BYTES;
constexpr int GEMM_SMEM = STAGES * STAGE_BYTES;        // 165888 B

template <bool FUSE_GELU, bool HALF_OUT>
__global__ void __launch_bounds__(256, 1)
k_gemm_f16(const __half* __restrict__ A, const __half* __restrict__ Bg,
           const float* __restrict__ bias, void* __restrict__ Cv,
           int M, int N, int K) {
    extern __shared__ uint32_t smem_w[];
    const uint32_t sbase = smem_u32(smem_w);

    const int tid = threadIdx.x;
    const int m0 = blockIdx.y * BM;
    const int n0 = blockIdx.x * BN;
    const int lane = tid & 31;
    const int warp = tid >> 5;
    const int g = lane >> 2, tig = lane & 3;
    const int wm = (warp & 1) * 64;        // 2 warps in M
    const int wn = (warp >> 1) * 64;       // 4 warps in N

    const int T = K / BKH;

    // ---- cp.async mapping: 384 rows x 128B per stage = 3072 x 16B chunks ----
    // thread covers col-chunk cw=(tid&7), rows r0=tid>>3 stepping +32:
    //   i=0..3  -> A rows r0+32i (0..127)
    //   i=4..11 -> B rows r0+32(i-4) (0..255)
    const int r0 = tid >> 3;
    const int cwB = (tid & 7) * 16;                 // byte offset within row
    const __half* aNext = A + (size_t)(m0 + r0) * K + (tid & 7) * 8;
    const __half* bNext = Bg + (size_t)(n0 + r0) * K + (tid & 7) * 8;
    const uint32_t sa_off = (uint32_t)(r0 * ROWB) + (uint32_t)cwB;
    const uint32_t sb_off = (uint32_t)A_WORDS * 4u + sa_off;

    auto issue_at = [&](uint32_t stoff) {
        const uint32_t sa = sbase + stoff + sa_off;
        const uint32_t sb = sbase + stoff + sb_off;
#pragma unroll
        for (int i = 0; i < 4; i++)
            cp_async16(sa + (uint32_t)(32 * i * ROWB), aNext + (size_t)(32 * i) * K);
#pragma unroll
        for (int i = 0; i < 8; i++)
            cp_async16(sb + (uint32_t)(32 * i * ROWB), bNext + (size_t)(32 * i) * K);
        cp_commit();
        aNext += BKH;
        bNext += BKH;
    };

    // ldmatrix base addresses (stage 0)
    const uint32_t aLdsm = sbase
        + (uint32_t)((wm + (lane & 15)) * ROWB)
        + (uint32_t)((lane >> 4) * 16);
    const uint32_t bLdsm = sbase + (uint32_t)A_WORDS * 4u
        + (uint32_t)((wn + ((lane >> 4) << 3) + (lane & 7)) * ROWB)
        + (uint32_t)(((lane >> 3) & 1) * 16);

    float acc[4][8][4];
#pragma unroll
    for (int mi = 0; mi < 4; mi++)
#pragma unroll
        for (int ni = 0; ni < 8; ni++)
#pragma unroll
            for (int q = 0; q < 4; q++) acc[mi][ni][q] = 0.f;

    issue_at(0);
    issue_at(STAGE_BYTES);

    uint32_t stoff_i = STAGE_LAST;    // smem offset for next issue (stage t+2)
    uint32_t stoff_c = 0;             // smem offset for current compute (stage t)

    for (int t = 0; t < T; ++t) {
        cp_wait<1>();                 // stage t landed
        __syncthreads();              // all reads of the buffer being refilled done
        if (t + 2 < T) issue_at(stoff_i);
        stoff_i = (stoff_i == STAGE_LAST) ? 0u : stoff_i + (uint32_t)STAGE_BYTES;

        const uint32_t aS = aLdsm + stoff_c;
        const uint32_t bS = bLdsm + stoff_c;
        stoff_c = (stoff_c == STAGE_LAST) ? 0u : stoff_c + (uint32_t)STAGE_BYTES;
#pragma unroll
        for (int k16 = 0; k16 < 4; ++k16) {          // 4 x K=16 per stage
            const uint32_t kb = (uint32_t)(k16 * 32); // 8 words = 32 B
            uint32_t bq[4][4];
#pragma unroll
            for (int nip = 0; nip < 4; ++nip)        // 4 LDSM: 8 n8k16 B frags
                ldsm_x4(bq[nip], bS + (uint32_t)(nip * 16 * ROWB) + kb);
            uint32_t af[4][4];
#pragma unroll
            for (int mi = 0; mi < 4; ++mi)           // 4 LDSM: 4 m16k16 A frags
                ldsm_x4(af[mi], aS + (uint32_t)(mi * 16 * ROWB) + kb);
#pragma unroll
            for (int mi = 0; mi < 4; ++mi)
#pragma unroll
                for (int ni = 0; ni < 8; ++ni)
                    mma_f16(acc[mi][ni], af[mi], bq[ni >> 1][2 * (ni & 1)],
                            bq[ni >> 1][2 * (ni & 1) + 1]);
        }
    }

    // ---- epilogue ----
#pragma unroll
    for (int mi = 0; mi < 4; ++mi) {
        const int row = m0 + wm + mi * 16 + g;
#pragma unroll
        for (int ni = 0; ni < 8; ++ni) {
            const int col = n0 + wn + ni * 8 + tig * 2;
            const float bv0 = bias[col], bv1 = bias[col + 1];
            float v00 = acc[mi][ni][0] + bv0;
            float v01 = acc[mi][ni][1] + bv1;
            float v10 = acc[mi][ni][2] + bv0;
            float v11 = acc[mi][ni][3] + bv1;
            if (FUSE_GELU) {
                v00 = gelu_exact(v00);
                v01 = gelu_exact(v01);
                v10 = gelu_exact(v10);
                v11 = gelu_exact(v11);
            }
            if (HALF_OUT) {
                __half* C = (__half*)Cv;
                *reinterpret_cast<__half2*>(&C[(size_t)row * N + col]) =
                    __floats2half2_rn(v00, v01);
                *reinterpret_cast<__half2*>(&C[(size_t)(row + 8) * N + col]) =
                    __floats2half2_rn(v10, v11);
            } else {
                float* C = (float*)Cv;
                *reinterpret_cast<float2*>(&C[(size_t)row * N + col])       = make_float2(v00, v01);
                *reinterpret_cast<float2*>(&C[(size_t)(row + 8) * N + col]) = make_float2(v10, v11);
            }
        }
    }
}

// ---------------- launch ----------------
extern "C" void kernel_launch(void* const* d_in, const int* in_sizes, int n_in,
                              void* d_out, int out_size) {
    const float* x   = (const float*)d_in[0];
    const float* c0a = (const float*)d_in[1];
    const float* c0b = (const float*)d_in[2];
    const float* c0c = (const float*)d_in[3];
    const float* b0  = (const float*)d_in[4];
    const float* c1a = (const float*)d_in[5];
    const float* c1b = (const float*)d_in[6];
    const float* c1c = (const float*)d_in[7];
    const float* b1  = (const float*)d_in[8];
    float* out = (float*)d_out;

    void *pW0, *pW1, *pXh, *pHh;
    cudaGetSymbolAddress(&pW0, g_W0h);
    cudaGetSymbolAddress(&pW1, g_W1h);
    cudaGetSymbolAddress(&pXh, g_Xh);
    cudaGetSymbolAddress(&pHh, g_Hh);
    __half* W0h = (__half*)pW0;
    __half* W1h = (__half*)pW1;
    __half* Xh  = (__half*)pXh;
    __half* Hh  = (__half*)pHh;

    cudaFuncSetAttribute(k_gemm_f16<true, true>,
                         cudaFuncAttributeMaxDynamicSharedMemorySize, GEMM_SMEM);
    cudaFuncSetAttribute(k_gemm_f16<false, false>,
                         cudaFuncAttributeMaxDynamicSharedMemorySize, GEMM_SMEM);

    // 1) convert x -> fp16
    k_x_to_h<<<2048, 1024>>>((const float4*)x, (__half2*)Xh, 8192 * 1024 / 4);
    // 2) materialize transposed TT weight matrices (fp16)
    k_build_w0t<<<4096, 256>>>(c0a, c0b, c0c);
    k_build_w1t<<<1024, 256>>>(c1a, c1b, c1c);
    // 3) Hh = fp16(gelu(Xh @ W0h^T + b0))   [8192 x 4096]
    k_gemm_f16<true, true><<<dim3(4096 / BN, 8192 / BM), 256, GEMM_SMEM>>>(
        Xh, W0h, b0, Hh, 8192, 4096, 1024);
    // 4) out = Hh @ W1h^T + b1              [8192 x 1024] fp32
    k_gemm_f16<false, false><<<dim3(1024 / BN, 8192 / BM), 256, GEMM_SMEM>>>(
        Hh, W1h, b1, out, 8192, 1024, 4096);
}

// round 11
// speedup vs baseline: 1.1210x; 1.0005x over previous
#include <cuda_runtime.h>
#include <cuda_fp16.h>
#include <cstdint>
#include <cstddef>

#define DEV __device__ __forceinline__

// ---------------- scratch (static device allocations: allowed) ----------------
__device__ __half g_W0h[4096u * 1024u];  // 8 MB, W0^T [out=4096][in=1024] fp16
__device__ __half g_W1h[1024u * 4096u];  // 8 MB, W1^T [out=1024][in=4096] fp16
__device__ __half g_Xh [8192u * 1024u];  // 16 MB, fp16 x
__device__ __half g_Hh [8192u * 4096u];  // 64 MB, fp16 gelu(h)

// ---------------- helpers ----------------
DEV uint32_t smem_u32(const void* p) { return (uint32_t)__cvta_generic_to_shared(p); }
DEV void cp_async16(uint32_t dst, const void* src) {
    asm volatile("cp.async.cg.shared.global [%0], [%1], 16;\n" :: "r"(dst), "l"(src));
}
DEV void cp_commit() { asm volatile("cp.async.commit_group;\n" ::: "memory"); }
template <int W> DEV void cp_wait() {
    asm volatile("cp.async.wait_group %0;\n" :: "n"(W) : "memory");
}
DEV void mma_f16(float* c, const uint32_t* a, const uint32_t b0, const uint32_t b1) {
    asm volatile(
        "mma.sync.aligned.m16n8k16.row.col.f32.f16.f16.f32 "
        "{%0,%1,%2,%3}, {%4,%5,%6,%7}, {%8,%9}, {%0,%1,%2,%3};\n"
        : "+f"(c[0]), "+f"(c[1]), "+f"(c[2]), "+f"(c[3])
        : "r"(a[0]), "r"(a[1]), "r"(a[2]), "r"(a[3]), "r"(b0), "r"(b1));
}
DEV void ldsm_x4(uint32_t* r, uint32_t addr) {
    asm volatile("ldmatrix.sync.aligned.m8n8.x4.shared.b16 {%0,%1,%2,%3}, [%4];"
                 : "=r"(r[0]), "=r"(r[1]), "=r"(r[2]), "=r"(r[3]) : "r"(addr));
}
// exact-erf gelu via the cheap erff polynomial path
DEV float gelu_exact(float x) {
    return 0.5f * x * (1.0f + erff(x * 0.70710678118654752f));
}

// ---------------- prologue: x (fp32) -> fp16 ----------------
__global__ void k_x_to_h(const float4* __restrict__ x, __half2* __restrict__ xh, int n4) {
    int idx = blockIdx.x * blockDim.x + threadIdx.x;
    if (idx < n4) {
        float4 v = x[idx];
        xh[2 * idx]     = __floats2half2_rn(v.x, v.y);
        xh[2 * idx + 1] = __floats2half2_rn(v.z, v.w);
    }
}

// ---------------- transposed TT weight builders (fp16 out, proven correct) ----
__global__ void k_build_w0t(const float* __restrict__ c0a,
                            const float* __restrict__ c0b,
                            const float* __restrict__ c0c) {
    __shared__ float a_sh[64], c_sh[64], b_sh[1024], bc[1024];
    const int m = blockIdx.x;
    const int o = m >> 8, p = (m >> 4) & 15, q = m & 15;
    const int t = threadIdx.x;

    if (t < 64) {                       // a_sh[i*8+r]
        int i = t >> 3, r = t & 7;
        a_sh[t] = c0a[(i * 16 + o) * 8 + r];
    } else if (t < 128) {               // c_sh[s*8+k]
        int tt = t - 64, s = tt >> 3, k = tt & 7;
        c_sh[tt] = c0c[(s * 8 + k) * 16 + q];
    }
    for (int idx = t; idx < 1024; idx += 256) {   // b_sh[(r*16+j)*8+s]
        int rj = idx >> 3, s = idx & 7;
        b_sh[idx] = c0b[(rj * 16 + p) * 8 + s];
    }
    __syncthreads();
    for (int idx = t; idx < 1024; idx += 256) {   // bc[(r*16+j)*8+k]
        int rj = idx >> 3, k = idx & 7;
        float acc = 0.f;
#pragma unroll
        for (int s = 0; s < 8; s++) acc = fmaf(b_sh[rj * 8 + s], c_sh[s * 8 + k], acc);
        bc[idx] = acc;
    }
    __syncthreads();
    float v[4];
#pragma unroll
    for (int d = 0; d < 4; d++) {
        int n = 4 * t + d;
        int i = n >> 7, j = (n >> 3) & 15, k = n & 7;
        float acc = 0.f;
#pragma unroll
        for (int r = 0; r < 8; r++) acc = fmaf(a_sh[i * 8 + r], bc[(r * 16 + j) * 8 + k], acc);
        v[d] = acc;
    }
    __half2* dst = reinterpret_cast<__half2*>(&g_W0h[(size_t)m * 1024 + 4 * t]);
    dst[0] = __floats2half2_rn(v[0], v[1]);
    dst[1] = __floats2half2_rn(v[2], v[3]);
}

__global__ void k_build_w1t(const float* __restrict__ c1a,
                            const float* __restrict__ c1b,
                            const float* __restrict__ c1c) {
    __shared__ float a_sh[128], c_sh[128], b_sh[1024], bc[2048];
    const int m = blockIdx.x;
    const int o = m >> 7, p = (m >> 3) & 15, q = m & 7;
    const int t = threadIdx.x;

    if (t < 128) {                      // a_sh[i*8+r]
        int i = t >> 3, r = t & 7;
        a_sh[t] = c1a[(i * 8 + o) * 8 + r];
    } else {                            // c_sh[s*16+k]
        int tt = t - 128, s = tt >> 4, k = tt & 15;
        c_sh[tt] = c1c[(s * 16 + k) * 8 + q];
    }
    for (int idx = t; idx < 1024; idx += 256) {   // b_sh[(r*16+j)*8+s]
        int rj = idx >> 3, s = idx & 7;
        b_sh[idx] = c1b[(rj * 16 + p) * 8 + s];
    }
    __syncthreads();
    for (int idx = t; idx < 2048; idx += 256) {   // bc[(r*16+j)*16+k]
        int rj = idx >> 4, k = idx & 15;
        float acc = 0.f;
#pragma unroll
        for (int s = 0; s < 8; s++) acc = fmaf(b_sh[rj * 8 + s], c_sh[s * 16 + k], acc);
        bc[idx] = acc;
    }
    __syncthreads();
    const int i = t >> 4, j = t & 15;   // n = 16t + k
    float v[16];
#pragma unroll
    for (int k = 0; k < 16; k++) {
        float acc = 0.f;
#pragma unroll
        for (int r = 0; r < 8; r++) acc = fmaf(a_sh[i * 8 + r], bc[(r * 16 + j) * 16 + k], acc);
        v[k] = acc;
    }
    __half2* dst = reinterpret_cast<__half2*>(&g_W1h[(size_t)m * 4096 + 16 * t]);
#pragma unroll
    for (int d = 0; d < 8; d++)
        dst[d] = __floats2half2_rn(v[2 * d], v[2 * d + 1]);
}

// ---------------- fp16 GEMM: C = act(A @ B^T + bias) ----------------
// A: [M][K] fp16 row-major; B: [N][K] fp16 row-major (weights pre-transposed).
// CTA tile 128(M) x 256(N), BK=64 halves, 3-stage cp.async ring.
// 256 threads = 8 warps in 2(M) x 4(N); warp tile 64x64 (acc 128 regs).
// Explicit k16 fragment double-buffering: LDSM of step k+1 issued before the
// 32 MMAs of step k, so crossbar latency hides under tensor work.
constexpr int BM = 128, BN = 256, BKH = 64, STAGES = 3;
constexpr int STRW = 36;                               // 32 words + 4 pad
constexpr int ROWB = STRW * 4;                         // 144 B row stride
constexpr int A_WORDS = BM * STRW;                     // 4608
constexpr int B_WORDS = BN * STRW;                     // 9216
constexpr int STAGE_WORDS = A_WORDS + B_WORDS;         // 13824
constexpr int STAGE_BYTES = STAGE_WORDS * 4;           // 55296
constexpr uint32_t STAGE_LAST = 2u * STAGE_BYTES;
constexpr int GEMM_SMEM = STAGES * STAGE_BYTES;        // 165888 B

template <bool FUSE_GELU, bool HALF_OUT>
__global__ void __launch_bounds__(256, 1)
k_gemm_f16(const __half* __restrict__ A, const __half* __restrict__ Bg,
           const float* __restrict__ bias, void* __restrict__ Cv,
           int M, int N, int K) {
    extern __shared__ uint32_t smem_w[];
    const uint32_t sbase = smem_u32(smem_w);

    const int tid = threadIdx.x;
    const int m0 = blockIdx.y * BM;
    const int n0 = blockIdx.x * BN;
    const int lane = tid & 31;
    const int warp = tid >> 5;
    const int g = lane >> 2, tig = lane & 3;
    const int wm = (warp & 1) * 64;        // 2 warps in M
    const int wn = (warp >> 1) * 64;       // 4 warps in N

    const int T = K / BKH;

    // ---- cp.async mapping: 384 rows x 128B per stage = 3072 x 16B chunks ----
    const int r0 = tid >> 3;
    const int cwB = (tid & 7) * 16;                 // byte offset within row
    const __half* aNext = A + (size_t)(m0 + r0) * K + (tid & 7) * 8;
    const __half* bNext = Bg + (size_t)(n0 + r0) * K + (tid & 7) * 8;
    const uint32_t sa_off = (uint32_t)(r0 * ROWB) + (uint32_t)cwB;
    const uint32_t sb_off = (uint32_t)A_WORDS * 4u + sa_off;

    auto issue_at = [&](uint32_t stoff) {
        const uint32_t sa = sbase + stoff + sa_off;
        const uint32_t sb = sbase + stoff + sb_off;
#pragma unroll
        for (int i = 0; i < 4; i++)
            cp_async16(sa + (uint32_t)(32 * i * ROWB), aNext + (size_t)(32 * i) * K);
#pragma unroll
        for (int i = 0; i < 8; i++)
            cp_async16(sb + (uint32_t)(32 * i * ROWB), bNext + (size_t)(32 * i) * K);
        cp_commit();
        aNext += BKH;
        bNext += BKH;
    };

    // ldmatrix base addresses (stage 0)
    const uint32_t aLdsm = sbase
        + (uint32_t)((wm + (lane & 15)) * ROWB)
        + (uint32_t)((lane >> 4) * 16);
    const uint32_t bLdsm = sbase + (uint32_t)A_WORDS * 4u
        + (uint32_t)((wn + ((lane >> 4) << 3) + (lane & 7)) * ROWB)
        + (uint32_t)(((lane >> 3) & 1) * 16);

    float acc[4][8][4];
#pragma unroll
    for (int mi = 0; mi < 4; mi++)
#pragma unroll
        for (int ni = 0; ni < 8; ni++)
#pragma unroll
            for (int q = 0; q < 4; q++) acc[mi][ni][q] = 0.f;

    issue_at(0);
    issue_at(STAGE_BYTES);

    uint32_t stoff_i = STAGE_LAST;    // smem offset for next issue (stage t+2)
    uint32_t stoff_c = 0;             // smem offset for current compute (stage t)

    uint32_t af[2][4][4];             // double-buffered A frags (4 m16k16)
    uint32_t bq[2][4][4];             // double-buffered B frags (8 n8k16)

    for (int t = 0; t < T; ++t) {
        cp_wait<1>();                 // stage t landed
        __syncthreads();              // all reads of the buffer being refilled done

        const uint32_t aS = aLdsm + stoff_c;
        const uint32_t bS = bLdsm + stoff_c;
        stoff_c = (stoff_c == STAGE_LAST) ? 0u : stoff_c + (uint32_t)STAGE_BYTES;

        // prime k16=0 fragments immediately after the barrier
#pragma unroll
        for (int nip = 0; nip < 4; ++nip)
            ldsm_x4(bq[0][nip], bS + (uint32_t)(nip * 16 * ROWB));
#pragma unroll
        for (int mi = 0; mi < 4; ++mi)
            ldsm_x4(af[0][mi], aS + (uint32_t)(mi * 16 * ROWB));

        if (t + 2 < T) issue_at(stoff_i);
        stoff_i = (stoff_i == STAGE_LAST) ? 0u : stoff_i + (uint32_t)STAGE_BYTES;

#pragma unroll
        for (int k16 = 0; k16 < 4; ++k16) {
            const int cur = k16 & 1, nxt = cur ^ 1;
            if (k16 < 3) {            // prefetch next k16's fragments
                const uint32_t kb = (uint32_t)((k16 + 1) * 32);
#pragma unroll
                for (int nip = 0; nip < 4; ++nip)
                    ldsm_x4(bq[nxt][nip], bS + (uint32_t)(nip * 16 * ROWB) + kb);
#pragma unroll
                for (int mi = 0; mi < 4; ++mi)
                    ldsm_x4(af[nxt][mi], aS + (uint32_t)(mi * 16 * ROWB) + kb);
            }
#pragma unroll
            for (int mi = 0; mi < 4; ++mi)
#pragma unroll
                for (int ni = 0; ni < 8; ++ni)
                    mma_f16(acc[mi][ni], af[cur][mi], bq[cur][ni >> 1][2 * (ni & 1)],
                            bq[cur][ni >> 1][2 * (ni & 1) + 1]);
        }
    }

    // ---- epilogue ----
#pragma unroll
    for (int mi = 0; mi < 4; ++mi) {
        const int row = m0 + wm + mi * 16 + g;
#pragma unroll
        for (int ni = 0; ni < 8; ++ni) {
            const int col = n0 + wn + ni * 8 + tig * 2;
            const float bv0 = bias[col], bv1 = bias[col + 1];
            float v00 = acc[mi][ni][0] + bv0;
            float v01 = acc[mi][ni][1] + bv1;
            float v10 = acc[mi][ni][2] + bv0;
            float v11 = acc[mi][ni][3] + bv1;
            if (FUSE_GELU) {
                v00 = gelu_exact(v00);
                v01 = gelu_exact(v01);
                v10 = gelu_exact(v10);
                v11 = gelu_exact(v11);
            }
            if (HALF_OUT) {
                __half* C = (__half*)Cv;
                *reinterpret_cast<__half2*>(&C[(size_t)row * N + col]) =
                    __floats2half2_rn(v00, v01);
                *reinterpret_cast<__half2*>(&C[(size_t)(row + 8) * N + col]) =
                    __floats2half2_rn(v10, v11);
            } else {
                float* C = (float*)Cv;
                *reinterpret_cast<float2*>(&C[(size_t)row * N + col])       = make_float2(v00, v01);
                *reinterpret_cast<float2*>(&C[(size_t)(row + 8) * N + col]) = make_float2(v10, v11);
            }
        }
    }
}

// ---------------- launch ----------------
extern "C" void kernel_launch(void* const* d_in, const int* in_sizes, int n_in,
                              void* d_out, int out_size) {
    const float* x   = (const float*)d_in[0];
    const float* c0a = (const float*)d_in[1];
    const float* c0b = (const float*)d_in[2];
    const float* c0c = (const float*)d_in[3];
    const float* b0  = (const float*)d_in[4];
    const float* c1a = (const float*)d_in[5];
    const float* c1b = (const float*)d_in[6];
    const float* c1c = (const float*)d_in[7];
    const float* b1  = (const float*)d_in[8];
    float* out = (float*)d_out;

    void *pW0, *pW1, *pXh, *pHh;
    cudaGetSymbolAddress(&pW0, g_W0h);
    cudaGetSymbolAddress(&pW1, g_W1h);
    cudaGetSymbolAddress(&pXh, g_Xh);
    cudaGetSymbolAddress(&pHh, g_Hh);
    __half* W0h = (__half*)pW0;
    __half* W1h = (__half*)pW1;
    __half* Xh  = (__half*)pXh;
    __half* Hh  = (__half*)pHh;

    cudaFuncSetAttribute(k_gemm_f16<true, true>,
                         cudaFuncAttributeMaxDynamicSharedMemorySize, GEMM_SMEM);
    cudaFuncSetAttribute(k_gemm_f16<false, false>,
                         cudaFuncAttributeMaxDynamicSharedMemorySize, GEMM_SMEM);

    // 1) convert x -> fp16
    k_x_to_h<<<2048, 1024>>>((const float4*)x, (__half2*)Xh, 8192 * 1024 / 4);
    // 2) materialize transposed TT weight matrices (fp16)
    k_build_w0t<<<4096, 256>>>(c0a, c0b, c0c);
    k_build_w1t<<<1024, 256>>>(c1a, c1b, c1c);
    // 3) Hh = fp16(gelu(Xh @ W0h^T + b0))   [8192 x 4096]
    k_gemm_f16<true, true><<<dim3(4096 / BN, 8192 / BM), 256, GEMM_SMEM>>>(
        Xh, W0h, b0, Hh, 8192, 4096, 1024);
    // 4) out = Hh @ W1h^T + b1              [8192 x 1024] fp32
    k_gemm_f16<false, false><<<dim3(1024 / BN, 8192 / BM), 256, GEMM_SMEM>>>(
        Hh, W1h, b1, out, 8192, 1024, 4096);
}

// round 12
// speedup vs baseline: 1.1528x; 1.0284x over previous
#include <cuda_runtime.h>
#include <cuda_fp16.h>
#include <cstdint>
#include <cstddef>

#define DEV __device__ __forceinline__

// ---------------- scratch (static device allocations: allowed) ----------------
__device__ __half g_W0h[4096u * 1024u];  // 8 MB, W0^T [out=4096][in=1024] fp16
__device__ __half g_W1h[1024u * 4096u];  // 8 MB, W1^T [out=1024][in=4096] fp16
__device__ __half g_Xh [8192u * 1024u];  // 16 MB, fp16 x
__device__ __half g_Hh [8192u * 4096u];  // 64 MB, fp16 gelu(h)

// ---------------- helpers ----------------
DEV uint32_t smem_u32(const void* p) { return (uint32_t)__cvta_generic_to_shared(p); }
DEV void cp_async16(uint32_t dst, const void* src) {
    asm volatile("cp.async.cg.shared.global [%0], [%1], 16;\n" :: "r"(dst), "l"(src));
}
DEV void cp_commit() { asm volatile("cp.async.commit_group;\n" ::: "memory"); }
template <int W> DEV void cp_wait() {
    asm volatile("cp.async.wait_group %0;\n" :: "n"(W) : "memory");
}
DEV void mma_f16(float* c, const uint32_t* a, const uint32_t b0, const uint32_t b1) {
    asm volatile(
        "mma.sync.aligned.m16n8k16.row.col.f32.f16.f16.f32 "
        "{%0,%1,%2,%3}, {%4,%5,%6,%7}, {%8,%9}, {%0,%1,%2,%3};\n"
        : "+f"(c[0]), "+f"(c[1]), "+f"(c[2]), "+f"(c[3])
        : "r"(a[0]), "r"(a[1]), "r"(a[2]), "r"(a[3]), "r"(b0), "r"(b1));
}
DEV void ldsm_x4(uint32_t* r, uint32_t addr) {
    asm volatile("ldmatrix.sync.aligned.m8n8.x4.shared.b16 {%0,%1,%2,%3}, [%4];"
                 : "=r"(r[0]), "=r"(r[1]), "=r"(r[2]), "=r"(r[3]) : "r"(addr));
}
// exact-erf gelu via the cheap erff polynomial path
DEV float gelu_exact(float x) {
    return 0.5f * x * (1.0f + erff(x * 0.70710678118654752f));
}

// ---------------- fused prologue ----------------
// blocks [0,4096)      : build W0^T row m = bid        (256 thr)
// blocks [4096,5120)   : build W1^T row m = bid-4096   (256 thr)
// blocks [5120,7168)   : x fp32 -> fp16, 4 float4/thr  (256 thr)
constexpr int PB_W0 = 4096, PB_W1 = 1024, PB_X = 2048;
constexpr int PB_TOTAL = PB_W0 + PB_W1 + PB_X;

__global__ void __launch_bounds__(256)
k_prologue(const float4* __restrict__ x,
           const float* __restrict__ c0a, const float* __restrict__ c0b,
           const float* __restrict__ c0c,
           const float* __restrict__ c1a, const float* __restrict__ c1b,
           const float* __restrict__ c1c) {
    const int bid = blockIdx.x;
    const int t = threadIdx.x;

    if (bid < PB_W0) {
        // ---- W0t[m][n] = sum_{r,s} c0a[(i*16+o)*8+r] c0b[((r*16+j)*16+p)*8+s] c0c[(s*8+k)*16+q]
        //      n=(i*16+j)*8+k (in 8,16,8), m=(o*16+p)*16+q (out 16,16,16)
        __shared__ float a_sh[64], c_sh[64], b_sh[1024], bc[1024];
        const int m = bid;
        const int o = m >> 8, p = (m >> 4) & 15, q = m & 15;

        if (t < 64) {                       // a_sh[i*8+r]
            int i = t >> 3, r = t & 7;
            a_sh[t] = c0a[(i * 16 + o) * 8 + r];
        } else if (t < 128) {               // c_sh[s*8+k]
            int tt = t - 64, s = tt >> 3, k = tt & 7;
            c_sh[tt] = c0c[(s * 8 + k) * 16 + q];
        }
        for (int idx = t; idx < 1024; idx += 256) {   // b_sh[(r*16+j)*8+s]
            int rj = idx >> 3, s = idx & 7;
            b_sh[idx] = c0b[(rj * 16 + p) * 8 + s];
        }
        __syncthreads();
        for (int idx = t; idx < 1024; idx += 256) {   // bc[(r*16+j)*8+k]
            int rj = idx >> 3, k = idx & 7;
            float acc = 0.f;
#pragma unroll
            for (int s = 0; s < 8; s++) acc = fmaf(b_sh[rj * 8 + s], c_sh[s * 8 + k], acc);
            bc[idx] = acc;
        }
        __syncthreads();
        float v[4];
#pragma unroll
        for (int d = 0; d < 4; d++) {
            int n = 4 * t + d;
            int i = n >> 7, j = (n >> 3) & 15, k = n & 7;
            float acc = 0.f;
#pragma unroll
            for (int r = 0; r < 8; r++) acc = fmaf(a_sh[i * 8 + r], bc[(r * 16 + j) * 8 + k], acc);
            v[d] = acc;
        }
        __half2* dst = reinterpret_cast<__half2*>(&g_W0h[(size_t)m * 1024 + 4 * t]);
        dst[0] = __floats2half2_rn(v[0], v[1]);
        dst[1] = __floats2half2_rn(v[2], v[3]);
    } else if (bid < PB_W0 + PB_W1) {
        // ---- W1t[m][n]: n=(i*16+j)*16+k (in 16,16,16), m=(o*16+p)*8+q (out 8,16,8)
        __shared__ float a_sh1[128], c_sh1[128], b_sh1[1024], bc1[2048];
        const int m = bid - PB_W0;
        const int o = m >> 7, p = (m >> 3) & 15, q = m & 7;

        if (t < 128) {                      // a_sh[i*8+r]
            int i = t >> 3, r = t & 7;
            a_sh1[t] = c1a[(i * 8 + o) * 8 + r];
        } else {                            // c_sh[s*16+k]
            int tt = t - 128, s = tt >> 4, k = tt & 15;
            c_sh1[tt] = c1c[(s * 16 + k) * 8 + q];
        }
        for (int idx = t; idx < 1024; idx += 256) {   // b_sh[(r*16+j)*8+s]
            int rj = idx >> 3, s = idx & 7;
            b_sh1[idx] = c1b[(rj * 16 + p) * 8 + s];
        }
        __syncthreads();
        for (int idx = t; idx < 2048; idx += 256) {   // bc[(r*16+j)*16+k]
            int rj = idx >> 4, k = idx & 15;
            float acc = 0.f;
#pragma unroll
            for (int s = 0; s < 8; s++) acc = fmaf(b_sh1[rj * 8 + s], c_sh1[s * 16 + k], acc);
            bc1[idx] = acc;
        }
        __syncthreads();
        const int i = t >> 4, j = t & 15;   // n = 16t + k
        float v[16];
#pragma unroll
        for (int k = 0; k < 16; k++) {
            float acc = 0.f;
#pragma unroll
            for (int r = 0; r < 8; r++) acc = fmaf(a_sh1[i * 8 + r], bc1[(r * 16 + j) * 16 + k], acc);
            v[k] = acc;
        }
        __half2* dst = reinterpret_cast<__half2*>(&g_W1h[(size_t)m * 4096 + 16 * t]);
#pragma unroll
        for (int d = 0; d < 8; d++)
            dst[d] = __floats2half2_rn(v[2 * d], v[2 * d + 1]);
    } else {
        // ---- x fp32 -> fp16: 4 float4 per thread, coalesced per sub-iteration
        const int xb = bid - (PB_W0 + PB_W1);
        __half2* xh = reinterpret_cast<__half2*>(g_Xh);
#pragma unroll
        for (int kk = 0; kk < 4; kk++) {
            int idx = xb * 1024 + kk * 256 + t;        // < 2M float4
            float4 v = x[idx];
            xh[2 * idx]     = __floats2half2_rn(v.x, v.y);
            xh[2 * idx + 1] = __floats2half2_rn(v.z, v.w);
        }
    }
}

// ---------------- fp16 GEMM: C = act(A @ B^T + bias) ----------------
// A: [M][K] fp16 row-major; B: [N][K] fp16 row-major (weights pre-transposed).
// CTA tile 128(M) x 256(N), BK=64 halves, 3-stage cp.async ring.
// 256 threads = 8 warps in 2(M) x 4(N); warp tile 64x64 (acc 128 regs).
// NOTE: proven at the legacy-HMMA instruction-rate ceiling (~0.27 MMA/cyc/SM);
// unchanged from Round 10/11 best.
constexpr int BM = 128, BN = 256, BKH = 64, STAGES = 3;
constexpr int STRW = 36;                               // 32 words + 4 pad
constexpr int ROWB = STRW * 4;                         // 144 B row stride
constexpr int A_WORDS = BM * STRW;                     // 4608
constexpr int B_WORDS = BN * STRW;                     // 9216
constexpr int STAGE_WORDS = A_WORDS + B_WORDS;         // 13824
constexpr int STAGE_BYTES = STAGE_WORDS * 4;           // 55296
constexpr uint32_t STAGE_LAST = 2u * STAGE_BYTES;
constexpr int GEMM_SMEM = STAGES * STAGE_BYTES;        // 165888 B

template <bool FUSE_GELU, bool HALF_OUT>
__global__ void __launch_bounds__(256, 1)
k_gemm_f16(const __half* __restrict__ A, const __half* __restrict__ Bg,
           const float* __restrict__ bias, void* __restrict__ Cv,
           int M, int N, int K) {
    extern __shared__ uint32_t smem_w[];
    const uint32_t sbase = smem_u32(smem_w);

    const int tid = threadIdx.x;
    const int m0 = blockIdx.y * BM;
    const int n0 = blockIdx.x * BN;
    const int lane = tid & 31;
    const int warp = tid >> 5;
    const int g = lane >> 2, tig = lane & 3;
    const int wm = (warp & 1) * 64;        // 2 warps in M
    const int wn = (warp >> 1) * 64;       // 4 warps in N

    const int T = K / BKH;

    // ---- cp.async mapping: 384 rows x 128B per stage = 3072 x 16B chunks ----
    const int r0 = tid >> 3;
    const int cwB = (tid & 7) * 16;                 // byte offset within row
    const __half* aNext = A + (size_t)(m0 + r0) * K + (tid & 7) * 8;
    const __half* bNext = Bg + (size_t)(n0 + r0) * K + (tid & 7) * 8;
    const uint32_t sa_off = (uint32_t)(r0 * ROWB) + (uint32_t)cwB;
    const uint32_t sb_off = (uint32_t)A_WORDS * 4u + sa_off;

    auto issue_at = [&](uint32_t stoff) {
        const uint32_t sa = sbase + stoff + sa_off;
        const uint32_t sb = sbase + stoff + sb_off;
#pragma unroll
        for (int i = 0; i < 4; i++)
            cp_async16(sa + (uint32_t)(32 * i * ROWB), aNext + (size_t)(32 * i) * K);
#pragma unroll
        for (int i = 0; i < 8; i++)
            cp_async16(sb + (uint32_t)(32 * i * ROWB), bNext + (size_t)(32 * i) * K);
        cp_commit();
        aNext += BKH;
        bNext += BKH;
    };

    // ldmatrix base addresses (stage 0)
    const uint32_t aLdsm = sbase
        + (uint32_t)((wm + (lane & 15)) * ROWB)
        + (uint32_t)((lane >> 4) * 16);
    const uint32_t bLdsm = sbase + (uint32_t)A_WORDS * 4u
        + (uint32_t)((wn + ((lane >> 4) << 3) + (lane & 7)) * ROWB)
        + (uint32_t)(((lane >> 3) & 1) * 16);

    float acc[4][8][4];
#pragma unroll
    for (int mi = 0; mi < 4; mi++)
#pragma unroll
        for (int ni = 0; ni < 8; ni++)
#pragma unroll
            for (int q = 0; q < 4; q++) acc[mi][ni][q] = 0.f;

    issue_at(0);
    issue_at(STAGE_BYTES);

    uint32_t stoff_i = STAGE_LAST;    // smem offset for next issue (stage t+2)
    uint32_t stoff_c = 0;             // smem offset for current compute (stage t)

    uint32_t af[2][4][4];             // double-buffered A frags (4 m16k16)
    uint32_t bq[2][4][4];             // double-buffered B frags (8 n8k16)

    for (int t = 0; t < T; ++t) {
        cp_wait<1>();                 // stage t landed
        __syncthreads();              // all reads of the buffer being refilled done

        const uint32_t aS = aLdsm + stoff_c;
        const uint32_t bS = bLdsm + stoff_c;
        stoff_c = (stoff_c == STAGE_LAST) ? 0u : stoff_c + (uint32_t)STAGE_BYTES;

        // prime k16=0 fragments immediately after the barrier
#pragma unroll
        for (int nip = 0; nip < 4; ++nip)
            ldsm_x4(bq[0][nip], bS + (uint32_t)(nip * 16 * ROWB));
#pragma unroll
        for (int mi = 0; mi < 4; ++mi)
            ldsm_x4(af[0][mi], aS + (uint32_t)(mi * 16 * ROWB));

        if (t + 2 < T) issue_at(stoff_i);
        stoff_i = (stoff_i == STAGE_LAST) ? 0u : stoff_i + (uint32_t)STAGE_BYTES;

#pragma unroll
        for (int k16 = 0; k16 < 4; ++k16) {
            const int cur = k16 & 1, nxt = cur ^ 1;
            if (k16 < 3) {            // prefetch next k16's fragments
                const uint32_t kb = (uint32_t)((k16 + 1) * 32);
#pragma unroll
                for (int nip = 0; nip < 4; ++nip)
                    ldsm_x4(bq[nxt][nip], bS + (uint32_t)(nip * 16 * ROWB) + kb);
#pragma unroll
                for (int mi = 0; mi < 4; ++mi)
                    ldsm_x4(af[nxt][mi], aS + (uint32_t)(mi * 16 * ROWB) + kb);
            }
#pragma unroll
            for (int mi = 0; mi < 4; ++mi)
#pragma unroll
                for (int ni = 0; ni < 8; ++ni)
                    mma_f16(acc[mi][ni], af[cur][mi], bq[cur][ni >> 1][2 * (ni & 1)],
                            bq[cur][ni >> 1][2 * (ni & 1) + 1]);
        }
    }

    // ---- epilogue ----
#pragma unroll
    for (int mi = 0; mi < 4; ++mi) {
        const int row = m0 + wm + mi * 16 + g;
#pragma unroll
        for (int ni = 0; ni < 8; ++ni) {
            const int col = n0 + wn + ni * 8 + tig * 2;
            const float bv0 = bias[col], bv1 = bias[col + 1];
            float v00 = acc[mi][ni][0] + bv0;
            float v01 = acc[mi][ni][1] + bv1;
            float v10 = acc[mi][ni][2] + bv0;
            float v11 = acc[mi][ni][3] + bv1;
            if (FUSE_GELU) {
                v00 = gelu_exact(v00);
                v01 = gelu_exact(v01);
                v10 = gelu_exact(v10);
                v11 = gelu_exact(v11);
            }
            if (HALF_OUT) {
                __half* C = (__half*)Cv;
                *reinterpret_cast<__half2*>(&C[(size_t)row * N + col]) =
                    __floats2half2_rn(v00, v01);
                *reinterpret_cast<__half2*>(&C[(size_t)(row + 8) * N + col]) =
                    __floats2half2_rn(v10, v11);
            } else {
                float* C = (float*)Cv;
                *reinterpret_cast<float2*>(&C[(size_t)row * N + col])       = make_float2(v00, v01);
                *reinterpret_cast<float2*>(&C[(size_t)(row + 8) * N + col]) = make_float2(v10, v11);
            }
        }
    }
}

// ---------------- launch ----------------
extern "C" void kernel_launch(void* const* d_in, const int* in_sizes, int n_in,
                              void* d_out, int out_size) {
    const float* x   = (const float*)d_in[0];
    const float* c0a = (const float*)d_in[1];
    const float* c0b = (const float*)d_in[2];
    const float* c0c = (const float*)d_in[3];
    const float* b0  = (const float*)d_in[4];
    const float* c1a = (const float*)d_in[5];
    const float* c1b = (const float*)d_in[6];
    const float* c1c = (const float*)d_in[7];
    const float* b1  = (const float*)d_in[8];
    float* out = (float*)d_out;

    void *pW0, *pW1, *pXh, *pHh;
    cudaGetSymbolAddress(&pW0, g_W0h);
    cudaGetSymbolAddress(&pW1, g_W1h);
    cudaGetSymbolAddress(&pXh, g_Xh);
    cudaGetSymbolAddress(&pHh, g_Hh);
    __half* W0h = (__half*)pW0;
    __half* W1h = (__half*)pW1;
    __half* Xh  = (__half*)pXh;
    __half* Hh  = (__half*)pHh;

    cudaFuncSetAttribute(k_gemm_f16<true, true>,
                         cudaFuncAttributeMaxDynamicSharedMemorySize, GEMM_SMEM);
    cudaFuncSetAttribute(k_gemm_f16<false, false>,
                         cudaFuncAttributeMaxDynamicSharedMemorySize, GEMM_SMEM);

    // 1) fused prologue: x->fp16 + both transposed TT weight matrices (one launch)
    k_prologue<<<PB_TOTAL, 256>>>((const float4*)x, c0a, c0b, c0c, c1a, c1b, c1c);
    // 2) Hh = fp16(gelu(Xh @ W0h^T + b0))   [8192 x 4096]
    k_gemm_f16<true, true><<<dim3(4096 / BN, 8192 / BM), 256, GEMM_SMEM>>>(
        Xh, W0h, b0, Hh, 8192, 4096, 1024);
    // 3) out = Hh @ W1h^T + b1              [8192 x 1024] fp32
    k_gemm_f16<false, false><<<dim3(1024 / BN, 8192 / BM), 256, GEMM_SMEM>>>(
        Hh, W1h, b1, out, 8192, 1024, 4096);
}

// round 14
// speedup vs baseline: 1.1963x; 1.0377x over previous
#include <cuda_runtime.h>
#include <cuda_fp16.h>
#include <cstdint>
#include <cstddef>

#define DEV __device__ __forceinline__

// ---------------- scratch (static device allocations: allowed) ----------------
__device__ __half g_W0h[4096u * 1024u];  // 8 MB, W0^T [out=4096][in=1024] fp16
__device__ __half g_W1h[1024u * 4096u];  // 8 MB, W1^T [out=1024][in=4096] fp16
__device__ __half g_Xh [8192u * 1024u];  // 16 MB, fp16 x
__device__ __half g_Hh [8192u * 4096u];  // 64 MB, fp16 gelu(h)

// ---------------- helpers ----------------
DEV uint32_t smem_u32(const void* p) { return (uint32_t)__cvta_generic_to_shared(p); }
DEV void cp_async16(uint32_t dst, const void* src) {
    asm volatile("cp.async.cg.shared.global [%0], [%1], 16;\n" :: "r"(dst), "l"(src));
}
DEV void cp_commit() { asm volatile("cp.async.commit_group;\n" ::: "memory"); }
template <int W> DEV void cp_wait() {
    asm volatile("cp.async.wait_group %0;\n" :: "n"(W) : "memory");
}
DEV void mma_f16(float* c, const uint32_t* a, const uint32_t b0, const uint32_t b1) {
    asm volatile(
        "mma.sync.aligned.m16n8k16.row.col.f32.f16.f16.f32 "
        "{%0,%1,%2,%3}, {%4,%5,%6,%7}, {%8,%9}, {%0,%1,%2,%3};\n"
        : "+f"(c[0]), "+f"(c[1]), "+f"(c[2]), "+f"(c[3])
        : "r"(a[0]), "r"(a[1]), "r"(a[2]), "r"(a[3]), "r"(b0), "r"(b1));
}
DEV void ldsm_x4(uint32_t* r, uint32_t addr) {
    asm volatile("ldmatrix.sync.aligned.m8n8.x4.shared.b16 {%0,%1,%2,%3}, [%4];"
                 : "=r"(r[0]), "=r"(r[1]), "=r"(r[2]), "=r"(r[3]) : "r"(addr));
}
// exact-erf gelu via the cheap erff polynomial path
DEV float gelu_exact(float x) {
    return 0.5f * x * (1.0f + erff(x * 0.70710678118654752f));
}

// ---------------- fused prologue ----------------
// blocks [0,1024)        : x fp32 -> fp16 (2 float4 -> 1 uint4, 4 per thread)
// blocks [1024,1280)     : build W0^T rows for (p,q); bc computed ONCE, 16 o-rows
// blocks [1280,1408)     : build W1^T rows for (p,q); bc computed ONCE, 8 o-rows
constexpr int PB_X = 1024, PB_W0 = 256, PB_W1 = 128;
constexpr int PB_TOTAL = PB_X + PB_W0 + PB_W1;

union H2x4 {
    uint4 u;
    __half2 h[4];
};

__global__ void __launch_bounds__(256)
k_prologue(const float4* __restrict__ x,
           const float* __restrict__ c0a, const float* __restrict__ c0b,
           const float* __restrict__ c0c,
           const float* __restrict__ c1a, const float* __restrict__ c1b,
           const float* __restrict__ c1c) {
    const int bid = blockIdx.x;
    const int t = threadIdx.x;

    if (bid < PB_X) {
        // ---- x fp32 -> fp16, 16B stores: thread packs 2 float4 -> 8 halves
        uint4* xh4 = reinterpret_cast<uint4*>(g_Xh);
#pragma unroll
        for (int kk = 0; kk < 4; kk++) {
            int idx = bid * 1024 + kk * 256 + t;       // < 1M
            float4 v0 = x[2 * idx];
            float4 v1 = x[2 * idx + 1];
            H2x4 o;
            o.h[0] = __floats2half2_rn(v0.x, v0.y);
            o.h[1] = __floats2half2_rn(v0.z, v0.w);
            o.h[2] = __floats2half2_rn(v1.x, v1.y);
            o.h[3] = __floats2half2_rn(v1.z, v1.w);
            xh4[idx] = o.u;
        }
    } else if (bid < PB_X + PB_W0) {
        // ---- W0t[(o*16+p)*16+q][(i*16+j)*8+k] = sum_r a[i,o,r] * bc[(r*16+j)*8+k]
        //      bc[(r*16+j)*8+k] = sum_s c0b[((r*16+j)*16+p)*8+s] * c0c[(s*8+k)*16+q]
        //      one block per (p,q); bc computed once, contracted for all 16 o.
        __shared__ float a_sh[1024], b_sh[1024], c_sh[64], bc[1024];
        const int pq = bid - PB_X;
        const int p = pq >> 4, q = pq & 15;

        for (int idx = t; idx < 1024; idx += 256) {
            a_sh[idx] = c0a[idx];                            // a[(i*16+o)*8+r]
            b_sh[idx] = c0b[(idx >> 3) * 128 + p * 8 + (idx & 7)]; // b[(rj)*8+s]
        }
        if (t < 64) {                                        // c_sh[s*8+k]
            int s = t >> 3, k = t & 7;
            c_sh[t] = c0c[(s * 8 + k) * 16 + q];
        }
        __syncthreads();
        for (int idx = t; idx < 1024; idx += 256) {          // bc[(rj)*8+k]
            int rj = idx >> 3, k = idx & 7;
            float acc = 0.f;
#pragma unroll
            for (int s = 0; s < 8; s++) acc = fmaf(b_sh[rj * 8 + s], c_sh[s * 8 + k], acc);
            bc[idx] = acc;
        }
        __syncthreads();
#pragma unroll 1
        for (int o = 0; o < 16; o++) {
            const int m = (o * 16 + p) * 16 + q;
            float v[4];
#pragma unroll
            for (int d = 0; d < 4; d++) {
                int n = 4 * t + d;
                int i = n >> 7, j = (n >> 3) & 15, k = n & 7;
                float acc = 0.f;
#pragma unroll
                for (int r = 0; r < 8; r++)
                    acc = fmaf(a_sh[(i * 16 + o) * 8 + r], bc[(r * 16 + j) * 8 + k], acc);
                v[d] = acc;
            }
            __half2* dst = reinterpret_cast<__half2*>(&g_W0h[(size_t)m * 1024 + 4 * t]);
            dst[0] = __floats2half2_rn(v[0], v[1]);
            dst[1] = __floats2half2_rn(v[2], v[3]);
        }
    } else {
        // ---- W1t[(o*16+p)*8+q][(i*16+j)*16+k] = sum_r a[i,o,r] * bc[(r*16+j)*16+k]
        //      bc[(r*16+j)*16+k] = sum_s c1b[((r*16+j)*16+p)*8+s] * c1c[(s*16+k)*8+q]
        //      one block per (p,q); bc once, contracted for all 8 o.
        __shared__ float a_sh1[1024], b_sh1[1024], c_sh1[128], bc1[2048];
        const int pq = bid - (PB_X + PB_W0);
        const int p = pq >> 3, q = pq & 7;

        for (int idx = t; idx < 1024; idx += 256) {
            a_sh1[idx] = c1a[idx];                           // a[(i*8+o)*8+r]
            b_sh1[idx] = c1b[(idx >> 3) * 128 + p * 8 + (idx & 7)];
        }
        if (t < 128) {                                       // c_sh[s*16+k]
            int s = t >> 4, k = t & 15;
            c_sh1[t] = c1c[(s * 16 + k) * 8 + q];
        }
        __syncthreads();
        for (int idx = t; idx < 2048; idx += 256) {          // bc[(rj)*16+k]
            int rj = idx >> 4, k = idx & 15;
            float acc = 0.f;
#pragma unroll
            for (int s = 0; s < 8; s++) acc = fmaf(b_sh1[rj * 8 + s], c_sh1[s * 16 + k], acc);
            bc1[idx] = acc;
        }
        __syncthreads();
        const int i = t >> 4, j = t & 15;                    // n = 16t + k
#pragma unroll 1
        for (int o = 0; o < 8; o++) {
            const int m = (o * 16 + p) * 8 + q;
            float v[16];
#pragma unroll
            for (int k = 0; k < 16; k++) {
                float acc = 0.f;
#pragma unroll
                for (int r = 0; r < 8; r++)
                    acc = fmaf(a_sh1[(i * 8 + o) * 8 + r], bc1[(r * 16 + j) * 16 + k], acc);
                v[k] = acc;
            }
            __half2* dst = reinterpret_cast<__half2*>(&g_W1h[(size_t)m * 4096 + 16 * t]);
#pragma unroll
            for (int d = 0; d < 8; d++)
                dst[d] = __floats2half2_rn(v[2 * d], v[2 * d + 1]);
        }
    }
}

// ---------------- fp16 GEMM: C = act(A @ B^T + bias) ----------------
// CTA tile 128(M) x 256(N), BK=64 halves, 3-stage cp.async ring.
// 256 threads = 8 warps in 2(M) x 4(N); warp tile 64x64 (acc 128 regs).
// At the legacy-HMMA instruction-rate ceiling; unchanged from Round 10-12 best.
constexpr int BM = 128, BN = 256, BKH = 64, STAGES = 3;
constexpr int STRW = 36;                               // 32 words + 4 pad
constexpr int ROWB = STRW * 4;                         // 144 B row stride
constexpr int A_WORDS = BM * STRW;                     // 4608
constexpr int B_WORDS = BN * STRW;                     // 9216
constexpr int STAGE_WORDS = A_WORDS + B_WORDS;         // 13824
constexpr int STAGE_BYTES = STAGE_WORDS * 4;           // 55296
constexpr uint32_t STAGE_LAST = 2u * STAGE_BYTES;
constexpr int GEMM_SMEM = STAGES * STAGE_BYTES;        // 165888 B

template <bool FUSE_GELU, bool HALF_OUT>
__global__ void __launch_bounds__(256, 1)
k_gemm_f16(const __half* __restrict__ A, const __half* __restrict__ Bg,
           const float* __restrict__ bias, void* __restrict__ Cv,
           int M, int N, int K) {
    extern __shared__ uint32_t smem_w[];
    const uint32_t sbase = smem_u32(smem_w);

    const int tid = threadIdx.x;
    const int m0 = blockIdx.y * BM;
    const int n0 = blockIdx.x * BN;
    const int lane = tid & 31;
    const int warp = tid >> 5;
    const int g = lane >> 2, tig = lane & 3;
    const int wm = (warp & 1) * 64;        // 2 warps in M
    const int wn = (warp >> 1) * 64;       // 4 warps in N

    const int T = K / BKH;

    // ---- cp.async mapping: 384 rows x 128B per stage = 3072 x 16B chunks ----
    const int r0 = tid >> 3;
    const int cwB = (tid & 7) * 16;                 // byte offset within row
    const __half* aNext = A + (size_t)(m0 + r0) * K + (tid & 7) * 8;
    const __half* bNext = Bg + (size_t)(n0 + r0) * K + (tid & 7) * 8;
    const uint32_t sa_off = (uint32_t)(r0 * ROWB) + (uint32_t)cwB;
    const uint32_t sb_off = (uint32_t)A_WORDS * 4u + sa_off;

    auto issue_at = [&](uint32_t stoff) {
        const uint32_t sa = sbase + stoff + sa_off;
        const uint32_t sb = sbase + stoff + sb_off;
#pragma unroll
        for (int i = 0; i < 4; i++)
            cp_async16(sa + (uint32_t)(32 * i * ROWB), aNext + (size_t)(32 * i) * K);
#pragma unroll
        for (int i = 0; i < 8; i++)
            cp_async16(sb + (uint32_t)(32 * i * ROWB), bNext + (size_t)(32 * i) * K);
        cp_commit();
        aNext += BKH;
        bNext += BKH;
    };

    // ldmatrix base addresses (stage 0)
    const uint32_t aLdsm = sbase
        + (uint32_t)((wm + (lane & 15)) * ROWB)
        + (uint32_t)((lane >> 4) * 16);
    const uint32_t bLdsm = sbase + (uint32_t)A_WORDS * 4u
        + (uint32_t)((wn + ((lane >> 4) << 3) + (lane & 7)) * ROWB)
        + (uint32_t)(((lane >> 3) & 1) * 16);

    float acc[4][8][4];
#pragma unroll
    for (int mi = 0; mi < 4; mi++)
#pragma unroll
        for (int ni = 0; ni < 8; ni++)
#pragma unroll
            for (int q = 0; q < 4; q++) acc[mi][ni][q] = 0.f;

    issue_at(0);
    issue_at(STAGE_BYTES);

    uint32_t stoff_i = STAGE_LAST;    // smem offset for next issue (stage t+2)
    uint32_t stoff_c = 0;             // smem offset for current compute (stage t)

    uint32_t af[2][4][4];             // double-buffered A frags (4 m16k16)
    uint32_t bq[2][4][4];             // double-buffered B frags (8 n8k16)

    for (int t = 0; t < T; ++t) {
        cp_wait<1>();                 // stage t landed
        __syncthreads();              // all reads of the buffer being refilled done

        const uint32_t aS = aLdsm + stoff_c;
        const uint32_t bS = bLdsm + stoff_c;
        stoff_c = (stoff_c == STAGE_LAST) ? 0u : stoff_c + (uint32_t)STAGE_BYTES;

        // prime k16=0 fragments immediately after the barrier
#pragma unroll
        for (int nip = 0; nip < 4; ++nip)
            ldsm_x4(bq[0][nip], bS + (uint32_t)(nip * 16 * ROWB));
#pragma unroll
        for (int mi = 0; mi < 4; ++mi)
            ldsm_x4(af[0][mi], aS + (uint32_t)(mi * 16 * ROWB));

        if (t + 2 < T) issue_at(stoff_i);
        stoff_i = (stoff_i == STAGE_LAST) ? 0u : stoff_i + (uint32_t)STAGE_BYTES;

#pragma unroll
        for (int k16 = 0; k16 < 4; ++k16) {
            const int cur = k16 & 1, nxt = cur ^ 1;
            if (k16 < 3) {            // prefetch next k16's fragments
                const uint32_t kb = (uint32_t)((k16 + 1) * 32);
#pragma unroll
                for (int nip = 0; nip < 4; ++nip)
                    ldsm_x4(bq[nxt][nip], bS + (uint32_t)(nip * 16 * ROWB) + kb);
#pragma unroll
                for (int mi = 0; mi < 4; ++mi)
                    ldsm_x4(af[nxt][mi], aS + (uint32_t)(mi * 16 * ROWB) + kb);
            }
#pragma unroll
            for (int mi = 0; mi < 4; ++mi)
#pragma unroll
                for (int ni = 0; ni < 8; ++ni)
                    mma_f16(acc[mi][ni], af[cur][mi], bq[cur][ni >> 1][2 * (ni & 1)],
                            bq[cur][ni >> 1][2 * (ni & 1) + 1]);
        }
    }

    // ---- epilogue ----
#pragma unroll
    for (int mi = 0; mi < 4; ++mi) {
        const int row = m0 + wm + mi * 16 + g;
#pragma unroll
        for (int ni = 0; ni < 8; ++ni) {
            const int col = n0 + wn + ni * 8 + tig * 2;
            const float bv0 = bias[col], bv1 = bias[col + 1];
            float v00 = acc[mi][ni][0] + bv0;
            float v01 = acc[mi][ni][1] + bv1;
            float v10 = acc[mi][ni][2] + bv0;
            float v11 = acc[mi][ni][3] + bv1;
            if (FUSE_GELU) {
                v00 = gelu_exact(v00);
                v01 = gelu_exact(v01);
                v10 = gelu_exact(v10);
                v11 = gelu_exact(v11);
            }
            if (HALF_OUT) {
                __half* C = (__half*)Cv;
                *reinterpret_cast<__half2*>(&C[(size_t)row * N + col]) =
                    __floats2half2_rn(v00, v01);
                *reinterpret_cast<__half2*>(&C[(size_t)(row + 8) * N + col]) =
                    __floats2half2_rn(v10, v11);
            } else {
                float* C = (float*)Cv;
                *reinterpret_cast<float2*>(&C[(size_t)row * N + col])       = make_float2(v00, v01);
                *reinterpret_cast<float2*>(&C[(size_t)(row + 8) * N + col]) = make_float2(v10, v11);
            }
        }
    }
}

// ---------------- launch ----------------
extern "C" void kernel_launch(void* const* d_in, const int* in_sizes, int n_in,
                              void* d_out, int out_size) {
    const float* x   = (const float*)d_in[0];
    const float* c0a = (const float*)d_in[1];
    const float* c0b = (const float*)d_in[2];
    const float* c0c = (const float*)d_in[3];
    const float* b0  = (const float*)d_in[4];
    const float* c1a = (const float*)d_in[5];
    const float* c1b = (const float*)d_in[6];
    const float* c1c = (const float*)d_in[7];
    const float* b1  = (const float*)d_in[8];
    float* out = (float*)d_out;

    void *pW0, *pW1, *pXh, *pHh;
    cudaGetSymbolAddress(&pW0, g_W0h);
    cudaGetSymbolAddress(&pW1, g_W1h);
    cudaGetSymbolAddress(&pXh, g_Xh);
    cudaGetSymbolAddress(&pHh, g_Hh);
    __half* W0h = (__half*)pW0;
    __half* W1h = (__half*)pW1;
    __half* Xh  = (__half*)pXh;
    __half* Hh  = (__half*)pHh;

    cudaFuncSetAttribute(k_gemm_f16<true, true>,
                         cudaFuncAttributeMaxDynamicSharedMemorySize, GEMM_SMEM);
    cudaFuncSetAttribute(k_gemm_f16<false, false>,
                         cudaFuncAttributeMaxDynamicSharedMemorySize, GEMM_SMEM);

    // 1) fused prologue: x->fp16 + both transposed TT weight matrices (dedup'd)
    k_prologue<<<PB_TOTAL, 256>>>((const float4*)x, c0a, c0b, c0c, c1a, c1b, c1c);
    // 2) Hh = fp16(gelu(Xh @ W0h^T + b0))   [8192 x 4096]
    k_gemm_f16<true, true><<<dim3(4096 / BN, 8192 / BM), 256, GEMM_SMEM>>>(
        Xh, W0h, b0, Hh, 8192, 4096, 1024);
    // 3) out = Hh @ W1h^T + b1              [8192 x 1024] fp32
    k_gemm_f16<false, false><<<dim3(1024 / BN, 8192 / BM), 256, GEMM_SMEM>>>(
        Hh, W1h, b1, out, 8192, 1024, 4096);
}